// round 6
// baseline (speedup 1.0000x reference)
#include <cuda_runtime.h>
#include <cstdint>
#include <math.h>

#define NAq 1152
#define NDq 736
#define NPq 512

#define SPLIT 4
#define APB (NAq / SPLIT)      // 288 angles per bp block
#define CH 4
#define NCHb (APB / CH)        // 72 chunks
#define CHP (CH * NDq)         // float2 entries per chunk (2944)
#define CHP4 (CHP / 2)         // float4 loads per chunk (1472)

// ---- geometry in double (compile-time folded) ----
#define VOXd (1.0 / 0.7)
#define Dd   (VOXd * 595.0)
#define DDd  (VOXd * 490.6)
#define DUd  (VOXd * 1.2858)
#define DSDd (Dd + DDd)

typedef unsigned long long u64;

// ---- device scratch (static allocation: allowed) ----
__device__ float  g_filt[1025];
__device__ float  g_hext[1472];          // h[|i-735|] * pi/(2*NA)
__device__ float4 g_trig4[NAq];          // (cos, sin, cos*K, sin*K)
__device__ float2 g_fp2[NAq * NDq];      // filtered rows as (v, v_next - v)
__device__ float  g_part[SPLIT][NPq * NPq];

__device__ __forceinline__ float frcp(float x) {
    float r;
    asm("rcp.approx.f32 %0, %1;" : "=f"(r) : "f"(x));
    return r;
}
__device__ __forceinline__ u64 pk2(float lo, float hi) {
    u64 r; asm("mov.b64 %0, {%1, %2};" : "=l"(r) : "f"(lo), "f"(hi)); return r;
}
__device__ __forceinline__ void upk2(float& lo, float& hi, u64 v) {
    asm("mov.b64 {%0, %1}, %2;" : "=f"(lo), "=f"(hi) : "l"(v));
}
__device__ __forceinline__ u64 fma2(u64 a, u64 b, u64 c) {
    u64 r; asm("fma.rn.f32x2 %0, %1, %2, %3;" : "=l"(r) : "l"(a), "l"(b), "l"(c)); return r;
}
__device__ __forceinline__ u64 add2(u64 a, u64 b) {
    u64 r; asm("add.rn.f32x2 %0, %1, %2;" : "=l"(r) : "l"(a), "l"(b)); return r;
}
__device__ __forceinline__ u64 mul2(u64 a, u64 b) {
    u64 r; asm("mul.rn.f32x2 %0, %1, %2;" : "=l"(r) : "l"(a), "l"(b)); return r;
}

__device__ __forceinline__ void cpasync16(unsigned int s, const void* g) {
    asm volatile("cp.async.cg.shared.global [%0], [%1], 16;" :: "r"(s), "l"(g));
}
__device__ __forceinline__ void cpasync_commit() {
    asm volatile("cp.async.commit_group;");
}
__device__ __forceinline__ void cpasync_wait0() {
    asm volatile("cp.async.wait_group 0;");
}

// ---------------------------------------------------------------------------
// Stage 0a: FILT[k] = 2*Re(FFT(f))[k] * Shepp-Logan window, k = 0..1024
// ---------------------------------------------------------------------------
__global__ void filt_kernel() {
    int k = blockIdx.x * blockDim.x + threadIdx.x;
    if (k > 1024) return;
    double s0 = 0.0, s1 = 0.0, s2 = 0.0, s3 = 0.0;
    for (int m = 0; m < 512; m += 4) {
        int j0 = 2 * m + 1, j1 = j0 + 2, j2 = j0 + 4, j3 = j0 + 6;
        float c0 = cospif((float)((k * j0) & 2047) * (1.0f / 1024.0f));
        float c1 = cospif((float)((k * j1) & 2047) * (1.0f / 1024.0f));
        float c2 = cospif((float)((k * j2) & 2047) * (1.0f / 1024.0f));
        float c3 = cospif((float)((k * j3) & 2047) * (1.0f / 1024.0f));
        s0 += (double)(c0 / ((float)j0 * (float)j0));
        s1 += (double)(c1 / ((float)j1 * (float)j1));
        s2 += (double)(c2 / ((float)j2 * (float)j2));
        s3 += (double)(c3 / ((float)j3 * (float)j3));
    }
    double four = 0.5 - (4.0 / (M_PI * M_PI)) * ((s0 + s1) + (s2 + s3));
    if (k > 0) {
        double om = M_PI * (double)k / 2048.0;
        four *= sin(om) / om;
    }
    g_filt[k] = (float)four;
}

// ---------------------------------------------------------------------------
// Stage 0b: h[d] = irfft(FILT)[d]. One block per d, 128 threads + reduction.
// ---------------------------------------------------------------------------
__global__ void __launch_bounds__(128) hker_kernel() {
    __shared__ double red[128];
    int d = blockIdx.x;
    int tid = threadIdx.x;
    double s = 0.0;
    for (int k = 1 + tid; k <= 1023; k += 128) {
        s += (double)g_filt[k] * (double)cospif((float)((k * d) & 2047) * (1.0f / 1024.0f));
    }
    red[tid] = s;
    __syncthreads();
    for (int w = 64; w > 0; w >>= 1) {
        if (tid < w) red[tid] += red[tid + w];
        __syncthreads();
    }
    if (tid == 0) {
        double t = (double)g_filt[0] + (double)g_filt[1024] * ((d & 1) ? -1.0 : 1.0)
                 + 2.0 * red[0];
        float h = (float)(t * (1.0 / 2048.0) * (M_PI / (2.0 * (double)NAq)));
        g_hext[735 - d] = h;
        g_hext[735 + d] = h;
    }
}

// ---------------------------------------------------------------------------
// Stage 0c: angle tables (+ premultiplied K variants)
// ---------------------------------------------------------------------------
__global__ void angle_kernel() {
    int a = blockIdx.x * blockDim.x + threadIdx.x;
    if (a >= NAq) return;
    double beta = 2.0 * M_PI * (double)a / (double)NAq + M_PI / 2.0;
    float cb = (float)cos(beta);
    float sb = (float)sin(beta);
    const float K = (float)(DSDd / DUd);
    g_trig4[a] = make_float4(cb, sb, cb * K, sb * K);
}

// ---------------------------------------------------------------------------
// Stage 1: filtering as linear convolution, 4 rows/block; emits (v, dv) pairs.
// ---------------------------------------------------------------------------
#define RB 4
__global__ void __launch_bounds__(256) conv_kernel(const float* __restrict__ sino) {
    __shared__ float s_s[RB][NDq];
    __shared__ float s_h[1536];
    int tid = threadIdx.x;
    int row0 = blockIdx.x * RB;
#pragma unroll
    for (int r = 0; r < RB; r++)
        for (int i = tid; i < NDq; i += 256)
            s_s[r][i] = sino[(row0 + r) * NDq + i];
    for (int i = tid; i < 1536; i += 256) s_h[i] = (i < 1471) ? g_hext[i] : 0.0f;
    __syncthreads();

    float acc[RB][3] = {};
    const float* h0 = s_h + tid + 735;
#pragma unroll 4
    for (int k = 0; k < NDq; k++) {
        float hv0 = h0[-k];
        float hv1 = h0[256 - k];
        float hv2 = h0[512 - k];
#pragma unroll
        for (int r = 0; r < RB; r++) {
            float sv = s_s[r][k];
            acc[r][0] = fmaf(sv, hv0, acc[r][0]);
            acc[r][1] = fmaf(sv, hv1, acc[r][1]);
            acc[r][2] = fmaf(sv, hv2, acc[r][2]);
        }
    }
    __syncthreads();
#pragma unroll
    for (int r = 0; r < RB; r++) {
        s_s[r][tid] = acc[r][0];
        s_s[r][tid + 256] = acc[r][1];
        if (tid < NDq - 512) s_s[r][tid + 512] = acc[r][2];
    }
    __syncthreads();
#pragma unroll
    for (int r = 0; r < RB; r++) {
        float2* dst = g_fp2 + (row0 + r) * NDq;
        for (int i = tid; i < NDq; i += 256) {
            float v = s_s[r][i];
            float vn = (i < NDq - 1) ? s_s[r][i + 1] : v;
            dst[i] = make_float2(v, vn - v);
        }
    }
}

// ---------------------------------------------------------------------------
// Stage 2: fan-beam backprojection, packed f32x2 arithmetic.
// Grid (16, 8, 4): 32x64 tile, lane = x, thread iterates 8 y (4 packed pairs).
// Floor via 2^23 magic trick (no F2I/I2F on fma pipe); rcp per sample (MUFU,
// hidden). cp.async double-buffered 4-angle chunks; staged trig float4.
// ---------------------------------------------------------------------------
__global__ void __launch_bounds__(256, 4) bp_kernel() {
    __shared__ float2 sbuf[2][CHP];      // 2 * 23552 B
    __shared__ float4 s_trig[2][CH];
    int tid = threadIdx.x;
    int z   = blockIdx.z;
    int lx  = tid & 31;                  // lane = x offset
    int wy  = tid >> 5;                  // warp = 8-row band
    int x   = blockIdx.x * 32 + lx;
    int y0  = blockIdx.y * 64 + wy * 8;

    float xs  = (float)x  - 255.5f;
    float ys0 = (float)y0 - 255.5f;

    const float Df = (float)Dd;
    const float Kf = (float)(DSDd / DUd);

    // tile classification: farthest-corner radius bound => detector idx bound
    float tx0 = (float)(blockIdx.x * 32) - 255.5f;
    float ty0 = (float)(blockIdx.y * 64) - 255.5f;
    float mx = fmaxf(fabsf(tx0), fabsf(tx0 + 31.0f));
    float my = fmaxf(fabsf(ty0), fabsf(ty0 + 63.0f));
    float rm = sqrtf(mx * mx + my * my);
    bool fast = (Kf * rm) < (366.9f * (Df - rm));

    // packed constants
    const u64 C369  = pk2(369.5f, 369.5f);            // 367.5 + 2 (index offset)
    const u64 MAGA  = pk2(8388607.5f, 8388607.5f);    // 2^23 - 0.5
    const u64 MAGS  = pk2(-8388608.0f, -8388608.0f);  // -2^23
    const u64 NEG1  = pk2(-1.0f, -1.0f);

    unsigned int sb0a = (unsigned int)__cvta_generic_to_shared(&sbuf[0][0]);
    unsigned int sb1a = (unsigned int)__cvta_generic_to_shared(&sbuf[1][0]);
    const float4* gsrc = (const float4*)(g_fp2 + z * APB * NDq);
    int abase = z * APB;

    // preload chunk 0 (+ its trig)
#pragma unroll
    for (int j = 0; j < 6; j++) {
        int idx = tid + j * 256;
        if (idx < CHP4) cpasync16(sb0a + idx * 16, gsrc + idx);
    }
    if (tid < CH) s_trig[0][tid] = g_trig4[abase + tid];
    cpasync_commit();
    cpasync_wait0();
    __syncthreads();

    u64 ACC[4] = {0ull, 0ull, 0ull, 0ull};

    for (int c = 0; c < NCHb; c++) {
        if (c + 1 < NCHb) {
            const float4* src = gsrc + (c + 1) * CHP4;
            unsigned int dsts = (c & 1) ? sb0a : sb1a;
#pragma unroll
            for (int j = 0; j < 6; j++) {
                int idx = tid + j * 256;
                if (idx < CHP4) cpasync16(dsts + idx * 16, src + idx);
            }
            if (tid < CH) s_trig[(c + 1) & 1][tid] = g_trig4[abase + (c + 1) * CH + tid];
        }
        cpasync_commit();

        const float2* buf = sbuf[c & 1];
        const float4* trg = s_trig[c & 1];

#pragma unroll
        for (int aa = 0; aa < CH; aa++) {
            float4 tg = trg[aa];
            float cb = tg.x, sb = tg.y, cbK = tg.z, sbK = tg.w;

            float den0 = fmaf(-ys0, sb, fmaf(-xs, cb, Df));
            float peK0 = fmaf(ys0, cbK, -(xs * sbK));
            float den1 = den0 - sb;
            float pk1  = peK0 + cbK;
            float sb2n = -(sb + sb);
            float cbK2 = cbK + cbK;
            u64 DEN  = pk2(den0, den1);
            u64 PK   = pk2(peK0, pk1);
            u64 SB2N = pk2(sb2n, sb2n);
            u64 CK2  = pk2(cbK2, cbK2);
            const float2* row_m2 = buf + aa * NDq - 2;

#pragma unroll
            for (int p = 0; p < 4; p++) {
                float d0, d1; upk2(d0, d1, DEN);
                float r0s = frcp(d0);
                float r1s = frcp(d1);
                u64 R = pk2(r0s, r1s);
                u64 U = fma2(PK, R, C369);       // iu + 2, per lane-pair
                u64 W = mul2(R, R);

                if (fast) {
                    u64 M  = add2(U, MAGA);      // 2^23 + floor(U)
                    u64 NF = add2(M, MAGS);      // floor(U) as float
                    u64 FR = fma2(NF, NEG1, U);  // frac
                    float mf0, mf1; upk2(mf0, mf1, M);
                    int n0 = __float_as_int(mf0) & 0x3FF;
                    int n1 = __float_as_int(mf1) & 0x3FF;
                    float2 v0 = row_m2[n0];
                    float2 v1 = row_m2[n1];
                    u64 VX = pk2(v0.x, v1.x);
                    u64 VY = pk2(v0.y, v1.y);
                    u64 VAL = fma2(FR, VY, VX);
                    ACC[p] = fma2(W, VAL, ACC[p]);
                } else {
                    float u0, u1; upk2(u0, u1, U);
                    float uc0 = fminf(fmaxf(u0, 1.0f), 738.5f);
                    float uc1 = fminf(fmaxf(u1, 1.0f), 738.5f);
                    float m0 = uc0 + 8388607.5f;
                    float m1 = uc1 + 8388607.5f;
                    int n0 = __float_as_int(m0) & 0x3FF;
                    int n1 = __float_as_int(m1) & 0x3FF;
                    float fr0 = uc0 - (m0 - 8388608.0f);
                    float fr1 = uc1 - (m1 - 8388608.0f);
                    bool ok0 = (unsigned)(n0 - 2) <= 734u;
                    bool ok1 = (unsigned)(n1 - 2) <= 734u;
                    int ic0 = min(max(n0, 2), 736);
                    int ic1 = min(max(n1, 2), 736);
                    float w0, w1; upk2(w0, w1, W);
                    w0 = ok0 ? w0 : 0.0f;
                    w1 = ok1 ? w1 : 0.0f;
                    float2 v0 = row_m2[ic0];
                    float2 v1 = row_m2[ic1];
                    float val0 = fmaf(fr0, v0.y, v0.x);
                    float val1 = fmaf(fr1, v1.y, v1.x);
                    u64 WW  = pk2(w0, w1);
                    u64 VAL = pk2(val0, val1);
                    ACC[p] = fma2(WW, VAL, ACC[p]);
                }

                DEN = add2(DEN, SB2N);
                PK  = add2(PK, CK2);
            }
        }

        cpasync_wait0();
        __syncthreads();
    }

    float* dst = g_part[z] + y0 * NPq + x;
#pragma unroll
    for (int p = 0; p < 4; p++) {
        float a0, a1; upk2(a0, a1, ACC[p]);
        dst[(2 * p) * NPq]     = a0;
        dst[(2 * p + 1) * NPq] = a1;
    }
}

// ---------------------------------------------------------------------------
// Stage 3: sum the 4 partial planes + HU normalization.
// ---------------------------------------------------------------------------
__global__ void __launch_bounds__(128) reduce_kernel(float* __restrict__ out) {
    const float A = (float)((Dd * Dd) * (1000.0 / 0.0192) / 4096.0);
    const float B = (float)(24.0 / 4096.0);
    int idx = blockIdx.x * 128 + threadIdx.x;      // float4 index
    float4 p0 = ((const float4*)g_part[0])[idx];
    float4 p1 = ((const float4*)g_part[1])[idx];
    float4 p2 = ((const float4*)g_part[2])[idx];
    float4 p3 = ((const float4*)g_part[3])[idx];
    float4 o;
    o.x = fmaf(A, (p0.x + p1.x) + (p2.x + p3.x), B);
    o.y = fmaf(A, (p0.y + p1.y) + (p2.y + p3.y), B);
    o.z = fmaf(A, (p0.z + p1.z) + (p2.z + p3.z), B);
    o.w = fmaf(A, (p0.w + p1.w) + (p2.w + p3.w), B);
    ((float4*)out)[idx] = o;
}

// ---------------------------------------------------------------------------
extern "C" void kernel_launch(void* const* d_in, const int* in_sizes, int n_in,
                              void* d_out, int out_size) {
    const float* sino = (const float*)d_in[0];
    float* out = (float*)d_out;

    filt_kernel<<<9, 128>>>();              // 1025 values
    hker_kernel<<<NDq, 128>>>();            // 736 values, block-parallel
    angle_kernel<<<9, 128>>>();             // 1152 angles + K-premult
    conv_kernel<<<NAq / RB, 256>>>(sino);   // filtered sinogram -> (v, dv) pairs
    dim3 grid(NPq / 32, NPq / 64, SPLIT);   // 16 x 8 x 4 = 512 blocks (1 wave)
    bp_kernel<<<grid, 256>>>();
    reduce_kernel<<<NPq * NPq / 4 / 128, 128>>>(out);
}

// round 7
// speedup vs baseline: 1.1204x; 1.1204x over previous
#include <cuda_runtime.h>
#include <cstdint>
#include <math.h>

#define NAq 1152
#define NDq 736
#define NPq 512

#define SPLIT 4
#define APB (NAq / SPLIT)      // 288 angles per bp block
#define CH 4
#define NCHb (APB / CH)        // 72 chunks
#define CHP (CH * NDq)         // float2 entries per chunk (2944)
#define CHP4 (CHP / 2)         // float4 loads per chunk (1472)

// ---- geometry in double (compile-time folded) ----
#define VOXd (1.0 / 0.7)
#define Dd   (VOXd * 595.0)
#define DDd  (VOXd * 490.6)
#define DUd  (VOXd * 1.2858)
#define DSDd (Dd + DDd)

typedef unsigned long long u64;

// ---- device scratch (static allocation: allowed) ----
__device__ float  g_filt[1025];
__device__ float  g_hext[1472];          // h[|i-735|] * pi/(2*NA)
__device__ float4 g_trig4[NAq];          // (cos, sin, cos*K, sin*K)
__device__ float2 g_fp2[NAq * NDq];      // filtered rows as (v, v_next - v)
__device__ float  g_part[SPLIT][NPq * NPq];

__device__ __forceinline__ float frcp(float x) {
    float r;
    asm("rcp.approx.f32 %0, %1;" : "=f"(r) : "f"(x));
    return r;
}
__device__ __forceinline__ u64 pk2(float lo, float hi) {
    u64 r; asm("mov.b64 %0, {%1, %2};" : "=l"(r) : "f"(lo), "f"(hi)); return r;
}
__device__ __forceinline__ void upk2(float& lo, float& hi, u64 v) {
    asm("mov.b64 {%0, %1}, %2;" : "=f"(lo), "=f"(hi) : "l"(v));
}
__device__ __forceinline__ u64 fma2(u64 a, u64 b, u64 c) {
    u64 r; asm("fma.rn.f32x2 %0, %1, %2, %3;" : "=l"(r) : "l"(a), "l"(b), "l"(c)); return r;
}
__device__ __forceinline__ u64 add2(u64 a, u64 b) {
    u64 r; asm("add.rn.f32x2 %0, %1, %2;" : "=l"(r) : "l"(a), "l"(b)); return r;
}
__device__ __forceinline__ u64 mul2(u64 a, u64 b) {
    u64 r; asm("mul.rn.f32x2 %0, %1, %2;" : "=l"(r) : "l"(a), "l"(b)); return r;
}

__device__ __forceinline__ void cpasync16(unsigned int s, const void* g) {
    asm volatile("cp.async.cg.shared.global [%0], [%1], 16;" :: "r"(s), "l"(g));
}
__device__ __forceinline__ void cpasync_commit() {
    asm volatile("cp.async.commit_group;");
}
__device__ __forceinline__ void cpasync_wait0() {
    asm volatile("cp.async.wait_group 0;");
}

// ---------------------------------------------------------------------------
// Stage 0a: FILT[k] = 2*Re(FFT(f))[k] * Shepp-Logan window, k = 0..1024
// ---------------------------------------------------------------------------
__global__ void filt_kernel() {
    int k = blockIdx.x * blockDim.x + threadIdx.x;
    if (k > 1024) return;
    double s0 = 0.0, s1 = 0.0, s2 = 0.0, s3 = 0.0;
    for (int m = 0; m < 512; m += 4) {
        int j0 = 2 * m + 1, j1 = j0 + 2, j2 = j0 + 4, j3 = j0 + 6;
        float c0 = cospif((float)((k * j0) & 2047) * (1.0f / 1024.0f));
        float c1 = cospif((float)((k * j1) & 2047) * (1.0f / 1024.0f));
        float c2 = cospif((float)((k * j2) & 2047) * (1.0f / 1024.0f));
        float c3 = cospif((float)((k * j3) & 2047) * (1.0f / 1024.0f));
        s0 += (double)(c0 / ((float)j0 * (float)j0));
        s1 += (double)(c1 / ((float)j1 * (float)j1));
        s2 += (double)(c2 / ((float)j2 * (float)j2));
        s3 += (double)(c3 / ((float)j3 * (float)j3));
    }
    double four = 0.5 - (4.0 / (M_PI * M_PI)) * ((s0 + s1) + (s2 + s3));
    if (k > 0) {
        double om = M_PI * (double)k / 2048.0;
        four *= sin(om) / om;
    }
    g_filt[k] = (float)four;
}

// ---------------------------------------------------------------------------
// Stage 0b: h[d] = irfft(FILT)[d]. One block per d, 128 threads + reduction.
// ---------------------------------------------------------------------------
__global__ void __launch_bounds__(128) hker_kernel() {
    __shared__ double red[128];
    int d = blockIdx.x;
    int tid = threadIdx.x;
    double s = 0.0;
    for (int k = 1 + tid; k <= 1023; k += 128) {
        s += (double)g_filt[k] * (double)cospif((float)((k * d) & 2047) * (1.0f / 1024.0f));
    }
    red[tid] = s;
    __syncthreads();
    for (int w = 64; w > 0; w >>= 1) {
        if (tid < w) red[tid] += red[tid + w];
        __syncthreads();
    }
    if (tid == 0) {
        double t = (double)g_filt[0] + (double)g_filt[1024] * ((d & 1) ? -1.0 : 1.0)
                 + 2.0 * red[0];
        float h = (float)(t * (1.0 / 2048.0) * (M_PI / (2.0 * (double)NAq)));
        g_hext[735 - d] = h;
        g_hext[735 + d] = h;
    }
}

// ---------------------------------------------------------------------------
// Stage 0c: angle tables (+ premultiplied K variants)
// ---------------------------------------------------------------------------
__global__ void angle_kernel() {
    int a = blockIdx.x * blockDim.x + threadIdx.x;
    if (a >= NAq) return;
    double beta = 2.0 * M_PI * (double)a / (double)NAq + M_PI / 2.0;
    float cb = (float)cos(beta);
    float sb = (float)sin(beta);
    const float K = (float)(DSDd / DUd);
    g_trig4[a] = make_float4(cb, sb, cb * K, sb * K);
}

// ---------------------------------------------------------------------------
// Stage 1: filtering as linear convolution, 4 rows/block; emits (v, dv) pairs.
// ---------------------------------------------------------------------------
#define RB 4
__global__ void __launch_bounds__(256) conv_kernel(const float* __restrict__ sino) {
    __shared__ float s_s[RB][NDq];
    __shared__ float s_h[1536];
    int tid = threadIdx.x;
    int row0 = blockIdx.x * RB;
#pragma unroll
    for (int r = 0; r < RB; r++)
        for (int i = tid; i < NDq; i += 256)
            s_s[r][i] = sino[(row0 + r) * NDq + i];
    for (int i = tid; i < 1536; i += 256) s_h[i] = (i < 1471) ? g_hext[i] : 0.0f;
    __syncthreads();

    float acc[RB][3] = {};
    const float* h0 = s_h + tid + 735;
#pragma unroll 4
    for (int k = 0; k < NDq; k++) {
        float hv0 = h0[-k];
        float hv1 = h0[256 - k];
        float hv2 = h0[512 - k];
#pragma unroll
        for (int r = 0; r < RB; r++) {
            float sv = s_s[r][k];
            acc[r][0] = fmaf(sv, hv0, acc[r][0]);
            acc[r][1] = fmaf(sv, hv1, acc[r][1]);
            acc[r][2] = fmaf(sv, hv2, acc[r][2]);
        }
    }
    __syncthreads();
#pragma unroll
    for (int r = 0; r < RB; r++) {
        s_s[r][tid] = acc[r][0];
        s_s[r][tid + 256] = acc[r][1];
        if (tid < NDq - 512) s_s[r][tid + 512] = acc[r][2];
    }
    __syncthreads();
#pragma unroll
    for (int r = 0; r < RB; r++) {
        float2* dst = g_fp2 + (row0 + r) * NDq;
        for (int i = tid; i < NDq; i += 256) {
            float v = s_s[r][i];
            float vn = (i < NDq - 1) ? s_s[r][i + 1] : v;
            dst[i] = make_float2(v, vn - v);
        }
    }
}

// ---------------------------------------------------------------------------
// Stage 2: fan-beam backprojection, packed f32x2, series-based 1/den.
// Grid (16, 8, 4): 32x64 tile, lane = x, thread iterates 8 y as 4 (even,odd)
// pairs. Exactly 2 rcps per angle-thread (one per pair phase); a packed
// 3rd-order series advances both lanes by dy=2 per step (rel err ~7e-8).
// Magic-number floor; cp.async double-buffered 4-angle chunks.
// ---------------------------------------------------------------------------
__global__ void __launch_bounds__(256, 4) bp_kernel() {
    __shared__ float2 sbuf[2][CHP];      // 2 * 23552 B
    __shared__ float4 s_trig[2][CH];
    int tid = threadIdx.x;
    int z   = blockIdx.z;
    int lx  = tid & 31;                  // lane = x offset
    int wy  = tid >> 5;                  // warp = 8-row band
    int x   = blockIdx.x * 32 + lx;
    int y0  = blockIdx.y * 64 + wy * 8;

    float xs  = (float)x  - 255.5f;
    float ys0 = (float)y0 - 255.5f;

    const float Df = (float)Dd;
    const float Kf = (float)(DSDd / DUd);

    // tile classification: farthest-corner radius bound => detector idx bound
    float tx0 = (float)(blockIdx.x * 32) - 255.5f;
    float ty0 = (float)(blockIdx.y * 64) - 255.5f;
    float mx = fmaxf(fabsf(tx0), fabsf(tx0 + 31.0f));
    float my = fmaxf(fabsf(ty0), fabsf(ty0 + 63.0f));
    float rm = sqrtf(mx * mx + my * my);
    bool fast = (Kf * rm) < (366.9f * (Df - rm));

    // packed constants
    const u64 C369  = pk2(369.5f, 369.5f);            // 367.5 + 2 (index offset)
    const u64 MAGA  = pk2(8388607.5f, 8388607.5f);    // 2^23 - 0.5
    const u64 MAGS  = pk2(-8388608.0f, -8388608.0f);  // -2^23
    const u64 NEG1  = pk2(-1.0f, -1.0f);

    unsigned int sb0a = (unsigned int)__cvta_generic_to_shared(&sbuf[0][0]);
    unsigned int sb1a = (unsigned int)__cvta_generic_to_shared(&sbuf[1][0]);
    const float4* gsrc = (const float4*)(g_fp2 + z * APB * NDq);
    int abase = z * APB;

    // preload chunk 0 (+ its trig)
#pragma unroll
    for (int j = 0; j < 6; j++) {
        int idx = tid + j * 256;
        if (idx < CHP4) cpasync16(sb0a + idx * 16, gsrc + idx);
    }
    if (tid < CH) s_trig[0][tid] = g_trig4[abase + tid];
    cpasync_commit();
    cpasync_wait0();
    __syncthreads();

    u64 ACC[4] = {0ull, 0ull, 0ull, 0ull};

    for (int c = 0; c < NCHb; c++) {
        if (c + 1 < NCHb) {
            const float4* src = gsrc + (c + 1) * CHP4;
            unsigned int dsts = (c & 1) ? sb0a : sb1a;
#pragma unroll
            for (int j = 0; j < 6; j++) {
                int idx = tid + j * 256;
                if (idx < CHP4) cpasync16(dsts + idx * 16, src + idx);
            }
            if (tid < CH) s_trig[(c + 1) & 1][tid] = g_trig4[abase + (c + 1) * CH + tid];
        }
        cpasync_commit();

        const float2* buf = sbuf[c & 1];
        const float4* trg = s_trig[c & 1];

#pragma unroll
        for (int aa = 0; aa < CH; aa++) {
            float4 tg = trg[aa];
            float cb = tg.x, sb = tg.y, cbK = tg.z, sbK = tg.w;

            // per-angle setup: rows y0 (lane0) and y0+1 (lane1)
            float den0 = fmaf(-ys0, sb, fmaf(-xs, cb, Df));
            float den1 = den0 - sb;
            float r0a  = frcp(den0);
            float r0b  = frcp(den1);
            float peK0 = fmaf(ys0, cbK, -(xs * sbK));
            u64 R0 = pk2(r0a, r0b);
            u64 R  = R0;
            u64 PK = pk2(peK0, peK0 + cbK);
            float sb2 = sb + sb;
            u64 E2 = mul2(pk2(sb2, sb2), R0);      // per-lane 2*sb*r0
            u64 CK2 = pk2(cbK + cbK, cbK + cbK);
            u64 T = 0ull;                           // packed (0.f, 0.f)
            const float2* row_m2 = buf + aa * NDq - 2;

#pragma unroll
            for (int p = 0; p < 4; p++) {
                u64 U = fma2(PK, R, C369);          // iu + 2 per lane
                u64 W = mul2(R, R);

                if (fast) {
                    u64 M  = add2(U, MAGA);         // 2^23 + floor(U)
                    u64 NF = add2(M, MAGS);         // floor(U) as float
                    u64 FR = fma2(NF, NEG1, U);     // frac
                    float mf0, mf1; upk2(mf0, mf1, M);
                    int n0 = __float_as_int(mf0) & 0x3FF;
                    int n1 = __float_as_int(mf1) & 0x3FF;
                    float2 v0 = row_m2[n0];
                    float2 v1 = row_m2[n1];
                    u64 VX = pk2(v0.x, v1.x);
                    u64 VY = pk2(v0.y, v1.y);
                    u64 VAL = fma2(FR, VY, VX);
                    ACC[p] = fma2(W, VAL, ACC[p]);
                } else {
                    float u0, u1; upk2(u0, u1, U);
                    float uc0 = fminf(fmaxf(u0, 1.0f), 738.5f);
                    float uc1 = fminf(fmaxf(u1, 1.0f), 738.5f);
                    float m0 = uc0 + 8388607.5f;
                    float m1 = uc1 + 8388607.5f;
                    int n0 = __float_as_int(m0) & 0x3FF;
                    int n1 = __float_as_int(m1) & 0x3FF;
                    float fr0 = uc0 - (m0 - 8388608.0f);
                    float fr1 = uc1 - (m1 - 8388608.0f);
                    bool ok0 = (unsigned)(n0 - 2) <= 734u;
                    bool ok1 = (unsigned)(n1 - 2) <= 734u;
                    int ic0 = min(max(n0, 2), 736);
                    int ic1 = min(max(n1, 2), 736);
                    float w0, w1; upk2(w0, w1, W);
                    w0 = ok0 ? w0 : 0.0f;
                    w1 = ok1 ? w1 : 0.0f;
                    float2 v0 = row_m2[ic0];
                    float2 v1 = row_m2[ic1];
                    float val0 = fmaf(fr0, v0.y, v0.x);
                    float val1 = fmaf(fr1, v1.y, v1.x);
                    u64 WW  = pk2(w0, w1);
                    u64 VAL = pk2(val0, val1);
                    ACC[p] = fma2(WW, VAL, ACC[p]);
                }

                // advance both lanes by dy = 2 via 3rd-order series:
                // r = r0 * (1 + t + t^2 + t^3),  t = (dy_total * sb) * r0
                if (p < 3) {
                    T = add2(T, E2);
                    u64 G = fma2(T, T, T);          // t + t^2
                    u64 F = fma2(G, T, T);          // t + t^2 + t^3
                    R = fma2(R0, F, R0);
                    PK = add2(PK, CK2);
                }
            }
        }

        cpasync_wait0();
        __syncthreads();
    }

    float* dst = g_part[z] + y0 * NPq + x;
#pragma unroll
    for (int p = 0; p < 4; p++) {
        float a0, a1; upk2(a0, a1, ACC[p]);
        dst[(2 * p) * NPq]     = a0;
        dst[(2 * p + 1) * NPq] = a1;
    }
}

// ---------------------------------------------------------------------------
// Stage 3: sum the 4 partial planes + HU normalization.
// ---------------------------------------------------------------------------
__global__ void __launch_bounds__(128) reduce_kernel(float* __restrict__ out) {
    const float A = (float)((Dd * Dd) * (1000.0 / 0.0192) / 4096.0);
    const float B = (float)(24.0 / 4096.0);
    int idx = blockIdx.x * 128 + threadIdx.x;      // float4 index
    float4 p0 = ((const float4*)g_part[0])[idx];
    float4 p1 = ((const float4*)g_part[1])[idx];
    float4 p2 = ((const float4*)g_part[2])[idx];
    float4 p3 = ((const float4*)g_part[3])[idx];
    float4 o;
    o.x = fmaf(A, (p0.x + p1.x) + (p2.x + p3.x), B);
    o.y = fmaf(A, (p0.y + p1.y) + (p2.y + p3.y), B);
    o.z = fmaf(A, (p0.z + p1.z) + (p2.z + p3.z), B);
    o.w = fmaf(A, (p0.w + p1.w) + (p2.w + p3.w), B);
    ((float4*)out)[idx] = o;
}

// ---------------------------------------------------------------------------
extern "C" void kernel_launch(void* const* d_in, const int* in_sizes, int n_in,
                              void* d_out, int out_size) {
    const float* sino = (const float*)d_in[0];
    float* out = (float*)d_out;

    filt_kernel<<<9, 128>>>();              // 1025 values
    hker_kernel<<<NDq, 128>>>();            // 736 values, block-parallel
    angle_kernel<<<9, 128>>>();             // 1152 angles + K-premult
    conv_kernel<<<NAq / RB, 256>>>(sino);   // filtered sinogram -> (v, dv) pairs
    dim3 grid(NPq / 32, NPq / 64, SPLIT);   // 16 x 8 x 4 = 512 blocks (1 wave)
    bp_kernel<<<grid, 256>>>();
    reduce_kernel<<<NPq * NPq / 4 / 128, 128>>>(out);
}